// round 14
// baseline (speedup 1.0000x reference)
#include <cuda_runtime.h>
#include <cstdint>

// One persistent kernel, 148 CTAs x 1024 threads.
// FAST PATH (verified per-run): indices follow flat(i) = (F0 + i*P) mod T,
//   row = flat >> shiftU, col = flat & mask  (units = power of two).
//   Phase 1: transpose x  +  fused verify + DETERMINISTIC scatter (no atomics).
//   barrier; compute: 4 independent f32x2 chains per half-warp, double-buffered
//   entry loads, guard-free inner loop (zero-padded slots).
// FALLBACK (any mismatch): atomic scatter + 2nd barrier, same compute loop.
#define GRID  148
#define TPB   1024
#define NWARP (TPB / 32)
#define MAX_UNITS 2048
#define CAP       512
#define MAX_INPUT 30016

__device__ float     g_xT[MAX_INPUT * 32];            // x transposed: [input_dim][32]
__device__ long long g_entries[MAX_UNITS * CAP + 32]; // {val_bits:32 | (row<<5):32} (+pad)
__device__ int       g_cursor[MAX_UNITS];             // fallback only (self-cleaning)
__device__ int       g_cta_ok[GRID];                  // per-CTA verification flags
__device__ unsigned  g_bar;                           // monotone barrier counter

__device__ __forceinline__ void grid_barrier() {
    __syncthreads();
    if (threadIdx.x == 0) {
        __threadfence();
        unsigned arrive = atomicAdd(&g_bar, 1u) + 1u;
        unsigned rem = arrive % GRID;
        unsigned target = rem ? (arrive + (GRID - rem)) : arrive;
        unsigned v;
        do {
            asm volatile("ld.acquire.gpu.global.u32 %0, [%1];" : "=r"(v) : "l"(&g_bar));
        } while ((int)(v - target) < 0);
    }
    __syncthreads();
}

// One f32x2 dual-batch FMA step for a packed entry {val:hi32, row<<5:lo32}.
#define ENTRY_STEP(acc, e) do {                                               \
    unsigned long long xx =                                                   \
        *(const unsigned long long*)(xbase + (unsigned)(e));                  \
    unsigned long long dd;                                                    \
    asm("mov.b64 %0, {%1, %1};" : "=l"(dd)                                    \
        : "r"((unsigned)((unsigned long long)(e) >> 32)));                    \
    asm("fma.rn.f32x2 %0, %1, %2, %0;" : "+l"(acc) : "l"(dd), "l"(xx));       \
} while (0)

__global__ void __launch_bounds__(TPB, 1)
fused_kernel(const float* __restrict__ x,
             const float* __restrict__ kv,
             const float* __restrict__ bias,
             const int*   __restrict__ ind,
             float* __restrict__ out,
             int nnz, int units, int batch, int input_dim)
{
    __shared__ __align__(16) unsigned long long s_part[NWARP][16];
    const int tid  = threadIdx.x;
    const int bid  = blockIdx.x;
    const int lane = tid & 31;
    const int warp = tid >> 5;
    const int gwarp = bid * NWARP + warp;
    const int2* ind2 = (const int2*)ind;
    const int4* ind4 = (const int4*)ind;

    // ---- dtype detect (int64 LE => odd 32-bit words all 0) --------------------
    int nchk = nnz < TPB ? nnz : TPB;
    int vv = (tid < nchk) ? ind[2 * tid + 1] : 0;
    const int is64 = __syncthreads_or(vv != 0) ? 0 : 1;

    // ---- derive linear-congruence model from first two entries ----------------
    int r0d, c0d, r1d, c1d;
    if (is64) { r0d = ind[0]; c0d = ind[2]; r1d = ind[4]; c1d = ind[6]; }
    else      { r0d = ind[0]; c0d = ind[1]; r1d = ind[2]; c1d = ind[3]; }
    const unsigned T  = (unsigned)input_dim * (unsigned)units;
    const bool upot   = units > 0 && (units & (units - 1)) == 0;
    const int shiftU  = __popc(units - 1);
    const unsigned F0 = (unsigned)r0d * (unsigned)units + (unsigned)c0d;
    const unsigned F1 = (unsigned)r1d * (unsigned)units + (unsigned)c1d;
    const unsigned P  = (F1 + T - (T ? (F0 % T) : 0u)) % (T ? T : 1u);
    const unsigned mask = (unsigned)units - 1;
    const unsigned d  = P & mask;
    bool structural = upot && (d & 1u) && nnz >= 2 && units <= MAX_UNITS
                      && F0 < T && F1 < T && batch <= 32
                      && input_dim <= MAX_INPUT
                      && (((unsigned)nnz - 1u) >> shiftU) < (CAP - 32);
    if (structural) {                 // uniqueness: period T/gcd(P,T) must cover nnz
        unsigned a = P, b = T;
        while (b) { unsigned t = a % b; a = b; b = t; }     // a = gcd(P,T) (P>0)
        structural = (a != 0) && (T / a >= (unsigned)nnz);
    }

    // ========== Phase 1a: transpose x -> g_xT[input][32]  (no smem/syncs) ======
    const int idim = input_dim <= MAX_INPUT ? input_dim : MAX_INPUT;
    if ((idim & 3) == 0) {
        int nblk = idim >> 3;
        const bool have_row = (lane < batch);
        const float4* xb = (const float4*)(x + (size_t)lane * input_dim);
        for (int blk = gwarp; blk < nblk; blk += GRID * NWARP) {
            int i0 = blk * 8;
            float4 v0 = make_float4(0.f, 0.f, 0.f, 0.f), v1 = v0;
            if (have_row) { v0 = xb[i0 >> 2]; v1 = xb[(i0 >> 2) + 1]; }
            float* dst = g_xT + i0 * 32 + lane;
            dst[0]   = v0.x; dst[32]  = v0.y; dst[64]  = v0.z; dst[96]  = v0.w;
            dst[128] = v1.x; dst[160] = v1.y; dst[192] = v1.z; dst[224] = v1.w;
        }
        for (int i = nblk * 8 + gwarp; i < idim; i += GRID * NWARP)
            g_xT[i * 32 + lane] = have_row ? x[(size_t)lane * input_dim + i] : 0.f;
    } else {
        for (int i = gwarp; i < idim; i += GRID * NWARP)
            g_xT[i * 32 + lane] = (lane < batch) ? x[(size_t)lane * input_dim + i] : 0.f;
    }

    // ========== Phase 1b: fused verify + deterministic scatter (coalesced) =====
    bool ok = structural;
    if (structural) {
        const unsigned S = GRID * TPB;
        unsigned i = (unsigned)(bid * TPB + tid);
        if (i < (unsigned)nnz) {
            unsigned flat = (unsigned)((F0 + (unsigned long long)i * P) % T);
            unsigned Dv   = (unsigned)(((unsigned long long)S * P) % T);
            for (; i < (unsigned)nnz; i += S) {
                int r, c;
                if (is64) { int4 w = ind4[i]; r = w.x; c = w.z; }
                else      { int2 w = ind2[i]; r = w.x; c = w.y; }
                float val = kv[i];                       // coalesced
                ok = ok && ((unsigned)c < (unsigned)units)
                        && ((unsigned)r < (unsigned)input_dim)
                        && (flat == (((unsigned)r << shiftU) + (unsigned)c));
                unsigned cc = flat & mask;               // model-derived (in-bounds)
                unsigned jj = i >> shiftU;               // < CAP-32 by structural guard
                g_entries[cc * CAP + jj] =
                    ((long long)__float_as_int(val) << 32)
                    | (unsigned)((flat >> shiftU) << 5);
                flat += Dv; if (flat >= T) flat -= T;
            }
        }
    }
    int cta_ok = __syncthreads_and(ok ? 1 : 0);
    if (tid == 0) g_cta_ok[bid] = cta_ok;

    grid_barrier();

    int myflag = (tid < GRID) ? g_cta_ok[tid] : 1;
    const int all_ok = __syncthreads_and(myflag);

    const int team = gwarp >> 1;
    const int half = gwarp & 1;
    const bool active = (team < units);

    // ========== FALLBACK scatter (only when model rejected) ====================
    if (!all_ok) {
        if (is64) {
            for (int i = bid * TPB + tid; i < nnz; i += GRID * TPB) {
                int4 w = ind4[i];
                float val = kv[i];
                if ((unsigned)w.z < (unsigned)units) {
                    int pos = atomicAdd(&g_cursor[w.z], 1);
                    if (pos < CAP - 32)
                        g_entries[w.z * CAP + pos] =
                            ((long long)__float_as_int(val) << 32) | (unsigned)(w.x << 5);
                }
            }
        } else {
            for (int i = bid * TPB + tid; i < nnz; i += GRID * TPB) {
                int2 w = ind2[i];
                float val = kv[i];
                if ((unsigned)w.y < (unsigned)units) {
                    int pos = atomicAdd(&g_cursor[w.y], 1);
                    if (pos < CAP - 32)
                        g_entries[w.y * CAP + pos] =
                            ((long long)__float_as_int(val) << 32) | (unsigned)(w.x << 5);
                }
            }
        }
        grid_barrier();
    }

    // ========== Compute: 4 chains/half-warp, double-buffered, guard-free =======
    // Entry class c4 = (half<<1)|hsel owns t ≡ c4 (mod 4); unroll x4 (stride 16).
    // Slots >= n are zero (never written; static zero-init) -> padded reads add 0.
    int n = 0;
    if (active) {
        if (all_ok) {
            unsigned xinv = d;                            // d^{-1} mod 2^32 (Newton)
            #pragma unroll
            for (int it = 0; it < 5; it++) xinv = xinv * (2u - d * xinv);
            unsigned cdelta = (((unsigned)team + (unsigned)units) - (F0 & mask)) & mask;
            unsigned i0 = (xinv * cdelta) & mask;
            n = (i0 < (unsigned)nnz)
                ? (int)((((unsigned)nnz - 1u - i0) >> shiftU) + 1u) : 0;
        } else {
            n = g_cursor[team]; n = n < (CAP - 32) ? n : (CAP - 32);
        }
    }
    const long long* ent = g_entries + (size_t)(active ? team : 0) * CAP;

    const int hsel  = lane >> 4;                      // half-warp id
    const int bpair = lane & 15;                      // batch pair index
    const int c4    = (half << 1) | hsel;             // entry class 0..3
    const float* xbase = g_xT + 2 * bpair;

    unsigned long long a0 = 0ULL, a1 = 0ULL, a2 = 0ULL, a3 = 0ULL;
    if (n > 0) {
        int t = c4;
        long long e0 = ent[t], e1 = ent[t + 4], e2 = ent[t + 8], e3 = ent[t + 12];
        while (t < n) {
            int tn = t + 16;                          // prefetch next group first
            long long f0 = ent[tn],     f1 = ent[tn + 4];
            long long f2 = ent[tn + 8], f3 = ent[tn + 12];
            ENTRY_STEP(a0, e0);
            ENTRY_STEP(a1, e1);
            ENTRY_STEP(a2, e2);
            ENTRY_STEP(a3, e3);
            e0 = f0; e1 = f1; e2 = f2; e3 = f3;
            t = tn;
        }
    }
    unsigned long long acc;
    asm("add.rn.f32x2 %0, %1, %2;" : "=l"(acc) : "l"(a0), "l"(a1));
    {
        unsigned long long s23;
        asm("add.rn.f32x2 %0, %1, %2;" : "=l"(s23) : "l"(a2), "l"(a3));
        asm("add.rn.f32x2 %0, %0, %1;" : "+l"(acc) : "l"(s23));
    }
    {   // combine the two half-warps (same batch pair, different entry classes)
        unsigned long long o = __shfl_xor_sync(0xffffffffu, acc, 16);
        asm("add.rn.f32x2 %0, %0, %1;" : "+l"(acc) : "l"(o));
    }
    if (half && hsel == 0) s_part[warp][bpair] = acc; // odd team-warp publishes
    __syncthreads();
    if (!half && active && hsel == 0) {
        unsigned long long o = s_part[warp + 1][bpair];
        asm("add.rn.f32x2 %0, %0, %1;" : "+l"(acc) : "l"(o));
        unsigned alo = (unsigned)acc, ahi = (unsigned)(acc >> 32);
        float bz = bias[team];
        int b0 = 2 * bpair, b1 = b0 + 1;
        if (b0 < batch) out[b0 * units + team] = tanhf(__uint_as_float(alo) + bz);
        if (b1 < batch) out[b1 * units + team] = tanhf(__uint_as_float(ahi) + bz);
    }
    if (!all_ok && !half && active && lane == 0)
        g_cursor[team] = 0;                           // self-clean (fallback)
}

extern "C" void kernel_launch(void* const* d_in, const int* in_sizes, int n_in,
                              void* d_out, int out_size) {
    const float* x    = (const float*)d_in[0];
    const float* kv   = (const float*)d_in[1];
    const float* bias = (const float*)d_in[2];
    const int*   ind  = (const int*)d_in[3];
    float* out = (float*)d_out;

    int nnz       = in_sizes[1];
    int units     = in_sizes[2];
    int batch     = out_size / units;          // 32
    int input_dim = in_sizes[0] / batch;       // 30000

    fused_kernel<<<GRID, TPB>>>(x, kv, bias, ind, out,
                                nnz, units, batch, input_dim);
}